// round 2
// baseline (speedup 1.0000x reference)
#include <cuda_runtime.h>

#define K_CODES 8192
#define C_DIM   64
#define N_TOK   16384
#define HW      1024
#define CHUNK   64
#define TPB     64

// output layout (float32, concatenated in reference return order)
#define O_ZQST 0
#define O_IDX  1048576
#define O_ZQ   1064960
#define O_EMB  2113536
#define O_CS   2637824
#define O_AVG  2646016

static __device__ float g_counts[K_CODES];
static __device__ float g_dw[K_CODES * C_DIM];
static __device__ float g_hn[K_CODES];
static __device__ float g_n;

__device__ __forceinline__ unsigned long long pk2(float lo, float hi) {
    unsigned long long r;
    asm("mov.b64 %0, {%1, %2};" : "=l"(r) : "f"(lo), "f"(hi));
    return r;
}
__device__ __forceinline__ void upk2(unsigned long long v, float& lo, float& hi) {
    asm("mov.b64 {%0, %1}, %2;" : "=f"(lo), "=f"(hi) : "l"(v));
}
__device__ __forceinline__ unsigned long long ffma2(unsigned long long a,
                                                    unsigned long long b,
                                                    unsigned long long c) {
    unsigned long long d;
    asm("fma.rn.f32x2 %0, %1, %2, %3;" : "=l"(d) : "l"(a), "l"(b), "l"(c));
    return d;
}
__device__ __forceinline__ void cp_async16(void* smem, const void* gmem) {
    unsigned s = (unsigned)__cvta_generic_to_shared(smem);
    asm volatile("cp.async.cg.shared.global [%0], [%1], 16;\n" :: "r"(s), "l"(gmem));
}
#define CP_COMMIT() asm volatile("cp.async.commit_group;\n" ::: "memory")
#define CP_WAIT(n)  asm volatile("cp.async.wait_group %0;\n" :: "n"(n) : "memory")

// ---------------------------------------------------------------------------
// zero scratch (counts + dw)
__global__ void k_zero() {
    int i = blockIdx.x * blockDim.x + threadIdx.x;
    if (i < K_CODES) g_counts[i] = 0.0f;
    if (i < K_CODES * C_DIM) g_dw[i] = 0.0f;
}

// half squared norms of codebook rows: g_hn[k] = 0.5 * sum_c e[k][c]^2
__global__ void k_hn(const float* __restrict__ emb) {
    int w = (blockIdx.x * blockDim.x + threadIdx.x) >> 5;
    int lane = threadIdx.x & 31;
    if (w < K_CODES) {
        const float* e = emb + w * C_DIM;
        float a = e[lane];
        float b = e[lane + 32];
        float s = a * a + b * b;
        #pragma unroll
        for (int o = 16; o > 0; o >>= 1) s += __shfl_xor_sync(0xffffffffu, s, o);
        if (lane == 0) g_hn[w] = 0.5f * s;
    }
}

// ---------------------------------------------------------------------------
// main: argmin over codebook + z_q/z_q_st/indices + count/dw accumulation
__global__ __launch_bounds__(TPB)
void k_main(const float* __restrict__ z, const float* __restrict__ emb,
            float* __restrict__ out) {
    __shared__ __align__(16) float sbuf[2][CHUNK * C_DIM];
    __shared__ __align__(16) float shn[2][CHUNK];

    const int tid = threadIdx.x;
    const int t = blockIdx.x * TPB + tid;     // token id = b*1024 + hw
    const int b = t >> 10;
    const int hw = t & 1023;
    const float* zp = z + (size_t)b * (C_DIM * HW) + hw;

    // token in registers, packed as 32 f32x2 channel pairs
    unsigned long long tok[32];
    #pragma unroll
    for (int j = 0; j < 32; j++) {
        float lo = zp[(2 * j) * HW];
        float hi = zp[(2 * j + 1) * HW];
        tok[j] = pk2(lo, hi);
    }

    // chunk loader: 64 codes x 64 floats = 1024 float4; 16 float4 per thread
    auto load_chunk = [&](int ci, int bufi) {
        const float4* src = (const float4*)(emb + (size_t)ci * CHUNK * C_DIM);
        float4* dst = (float4*)sbuf[bufi];
        #pragma unroll
        for (int i = 0; i < 16; i++)
            cp_async16(dst + i * TPB + tid, src + i * TPB + tid);
        if (tid < CHUNK / 4)
            cp_async16((float4*)shn[bufi] + tid,
                       (const float4*)(g_hn + ci * CHUNK) + tid);
    };

    float best = -3.4e38f;
    int bi = 0;

    load_chunk(0, 0);
    CP_COMMIT();

    const int NC = K_CODES / CHUNK;   // 128
    for (int ci = 0; ci < NC; ci++) {
        if (ci + 1 < NC) {
            load_chunk(ci + 1, (ci + 1) & 1);
            CP_COMMIT();
            CP_WAIT(1);
        } else {
            CP_WAIT(0);
        }
        __syncthreads();

        const float* rowbase = sbuf[ci & 1];
        const float* hnb = shn[ci & 1];

        #pragma unroll 2
        for (int kk = 0; kk < CHUNK; kk++) {
            const ulonglong2* cp2 = (const ulonglong2*)(rowbase + kk * C_DIM);
            unsigned long long a0 = pk2(-hnb[kk], 0.0f);  // fold -0.5||e||^2
            unsigned long long a1 = pk2(0.0f, 0.0f);
            #pragma unroll
            for (int j = 0; j < 16; j++) {
                ulonglong2 v = cp2[j];                     // broadcast LDS.128
                a0 = ffma2(tok[2 * j],     v.x, a0);
                a1 = ffma2(tok[2 * j + 1], v.y, a1);
            }
            float s0, s1, s2, s3;
            upk2(a0, s0, s1);
            upk2(a1, s2, s3);
            float s = (s0 + s1) + (s2 + s3);               // x.e - 0.5||e||^2
            int kidx = ci * CHUNK + kk;
            if (s > best) { best = s; bi = kidx; }         // strict > => first argmin
        }
        __syncthreads();
    }

    // ---- epilogue ----
    out[O_IDX + t] = (float)bi;
    atomicAdd(&g_counts[bi], 1.0f);

    const float4* er = (const float4*)(emb + (size_t)bi * C_DIM);
    float* dwp = g_dw + (size_t)bi * C_DIM;
    float* zq   = out + O_ZQ   + (size_t)b * (C_DIM * HW) + hw;
    float* zqst = out + O_ZQST + (size_t)b * (C_DIM * HW) + hw;

    #pragma unroll
    for (int j = 0; j < 16; j++) {
        float4 q = er[j];
        float x0, x1, x2, x3;
        upk2(tok[2 * j], x0, x1);
        upk2(tok[2 * j + 1], x2, x3);
        int c = 4 * j;
        zq[(c + 0) * HW] = q.x;
        zq[(c + 1) * HW] = q.y;
        zq[(c + 2) * HW] = q.z;
        zq[(c + 3) * HW] = q.w;
        zqst[(c + 0) * HW] = x0 + (q.x - x0);
        zqst[(c + 1) * HW] = x1 + (q.y - x1);
        zqst[(c + 2) * HW] = x2 + (q.z - x2);
        zqst[(c + 3) * HW] = x3 + (q.w - x3);
        atomicAdd(dwp + c + 0, x0);
        atomicAdd(dwp + c + 1, x1);
        atomicAdd(dwp + c + 2, x2);
        atomicAdd(dwp + c + 3, x3);
    }
}

// ---------------------------------------------------------------------------
// new_cluster_size + total n (single block)
__global__ void k_cs(const float* __restrict__ cs, float* __restrict__ out) {
    const float OMD = (float)(1.0 - 0.99);
    int tid = threadIdx.x;
    float loc = 0.0f;
    for (int k = tid; k < K_CODES; k += 1024) {
        float v = 0.99f * cs[k] + OMD * g_counts[k];
        out[O_CS + k] = v;
        loc += v;
    }
    __shared__ float red[32];
    #pragma unroll
    for (int o = 16; o > 0; o >>= 1) loc += __shfl_xor_sync(0xffffffffu, loc, o);
    if ((tid & 31) == 0) red[tid >> 5] = loc;
    __syncthreads();
    if (tid < 32) {
        float v = red[tid];
        #pragma unroll
        for (int o = 16; o > 0; o >>= 1) v += __shfl_xor_sync(0xffffffffu, v, o);
        if (tid == 0) g_n = v;
    }
}

// new_embedding_avg + new_embedding
__global__ void k_emb(const float* __restrict__ cs, const float* __restrict__ avg,
                      float* __restrict__ out) {
    const float OMD = (float)(1.0 - 0.99);
    const float EPSF = 1e-5f;
    int i = blockIdx.x * blockDim.x + threadIdx.x;
    if (i >= K_CODES * C_DIM) return;
    int k = i >> 6;
    float ncs = 0.99f * cs[k] + OMD * g_counts[k];
    float navg = 0.99f * avg[i] + OMD * g_dw[i];
    float n = g_n;
    float denom = (ncs + EPSF) / (n + (float)K_CODES * EPSF) * n;
    out[O_EMB + i] = navg / denom;
    out[O_AVG + i] = navg;
}

// ---------------------------------------------------------------------------
extern "C" void kernel_launch(void* const* d_in, const int* in_sizes, int n_in,
                              void* d_out, int out_size) {
    const float* z    = (const float*)d_in[0];  // z_e [16,64,32,32]
    const float* emb  = (const float*)d_in[1];  // embedding [8192,64]
    const float* cs   = (const float*)d_in[2];  // cluster_size [8192]
    const float* avg  = (const float*)d_in[3];  // embedding_avg [8192,64]
    float* out = (float*)d_out;

    k_zero<<<(K_CODES * C_DIM + 255) / 256, 256>>>();
    k_hn<<<(K_CODES * 32 + 255) / 256, 256>>>(emb);
    k_main<<<N_TOK / TPB, TPB>>>(z, emb, out);
    k_cs<<<1, 1024>>>(cs, out);
    k_emb<<<(K_CODES * C_DIM + 255) / 256, 256>>>(cs, avg, out);
}

// round 3
// speedup vs baseline: 1.3432x; 1.3432x over previous
#include <cuda_runtime.h>

#define K_CODES 8192
#define C_DIM   64
#define N_TOK   16384
#define HW      1024
#define CHUNK   32
#define TPB     64
#define KSPLIT  8
#define KPB     (K_CODES / KSPLIT)   // 1024 codes per block
#define NCH     (KPB / CHUNK)        // 32 chunks

// output layout (float32, concatenated in reference return order)
#define O_ZQST 0
#define O_IDX  1048576
#define O_ZQ   1064960
#define O_EMB  2113536
#define O_CS   2637824
#define O_AVG  2646016

static __device__ float g_counts[K_CODES];
static __device__ float g_dw[K_CODES * C_DIM];
static __device__ float g_hn[K_CODES];
static __device__ unsigned long long g_key[N_TOK];
static __device__ float g_n;

typedef unsigned long long u64;
typedef unsigned int u32;

__device__ __forceinline__ u64 pk2(float lo, float hi) {
    u64 r;
    asm("mov.b64 %0, {%1, %2};" : "=l"(r) : "f"(lo), "f"(hi));
    return r;
}
__device__ __forceinline__ void upk2(u64 v, float& lo, float& hi) {
    asm("mov.b64 {%0, %1}, %2;" : "=f"(lo), "=f"(hi) : "l"(v));
}
__device__ __forceinline__ u64 ffma2(u64 a, u64 b, u64 c) {
    u64 d;
    asm("fma.rn.f32x2 %0, %1, %2, %3;" : "=l"(d) : "l"(a), "l"(b), "l"(c));
    return d;
}
__device__ __forceinline__ void cp_async16(void* smem, const void* gmem) {
    unsigned s = (unsigned)__cvta_generic_to_shared(smem);
    asm volatile("cp.async.cg.shared.global [%0], [%1], 16;\n" :: "r"(s), "l"(gmem));
}
#define CP_COMMIT() asm volatile("cp.async.commit_group;\n" ::: "memory")
#define CP_WAIT(n)  asm volatile("cp.async.wait_group %0;\n" :: "n"(n) : "memory")

// ---------------------------------------------------------------------------
// zero scratch (counts + dw) and init keys
__global__ void k_init() {
    int i = blockIdx.x * blockDim.x + threadIdx.x;
    if (i < K_CODES) g_counts[i] = 0.0f;
    if (i < K_CODES * C_DIM) g_dw[i] = 0.0f;
    if (i < N_TOK) g_key[i] = 0xFFFFFFFFFFFFFFFFULL;
}

// half squared norms of codebook rows: g_hn[k] = 0.5 * sum_c e[k][c]^2
__global__ void k_hn(const float* __restrict__ emb) {
    int w = (blockIdx.x * blockDim.x + threadIdx.x) >> 5;
    int lane = threadIdx.x & 31;
    if (w < K_CODES) {
        const float* e = emb + w * C_DIM;
        float a = e[lane];
        float b = e[lane + 32];
        float s = a * a + b * b;
        #pragma unroll
        for (int o = 16; o > 0; o >>= 1) s += __shfl_xor_sync(0xffffffffu, s, o);
        if (lane == 0) g_hn[w] = 0.5f * s;
    }
}

// ---------------------------------------------------------------------------
// distance + argmin over a K-slice; merge across slices via atomicMin(u64 key)
__global__ __launch_bounds__(TPB, 6)
void k_dist(const float* __restrict__ z, const float* __restrict__ emb) {
    __shared__ __align__(16) float sbuf[2][CHUNK * C_DIM];
    __shared__ __align__(16) float shn[2][CHUNK];

    const int tid = threadIdx.x;
    const int t = blockIdx.x * TPB + tid;     // token id = b*1024 + hw
    const int b = t >> 10;
    const int hw = t & 1023;
    const int kbase = blockIdx.y * KPB;
    const float* zp = z + (size_t)b * (C_DIM * HW) + hw;

    // token in registers, packed as 32 f32x2 channel pairs
    u64 tok[32];
    #pragma unroll
    for (int j = 0; j < 32; j++) {
        float lo = zp[(2 * j) * HW];
        float hi = zp[(2 * j + 1) * HW];
        tok[j] = pk2(lo, hi);
    }

    // chunk loader: 32 codes x 64 floats = 512 float4; 8 float4 per thread
    auto load_chunk = [&](int ci, int bufi) {
        const float4* src = (const float4*)(emb + (size_t)(kbase + ci * CHUNK) * C_DIM);
        float4* dst = (float4*)sbuf[bufi];
        #pragma unroll
        for (int i = 0; i < 8; i++)
            cp_async16(dst + i * TPB + tid, src + i * TPB + tid);
        if (tid < CHUNK / 4)
            cp_async16((float4*)shn[bufi] + tid,
                       (const float4*)(g_hn + kbase + ci * CHUNK) + tid);
    };

    float best = -3.4e38f;
    int bi = kbase;

    load_chunk(0, 0);
    CP_COMMIT();

    for (int ci = 0; ci < NCH; ci++) {
        if (ci + 1 < NCH) {
            load_chunk(ci + 1, (ci + 1) & 1);
            CP_COMMIT();
            CP_WAIT(1);
        } else {
            CP_WAIT(0);
        }
        __syncthreads();

        const float* rowbase = sbuf[ci & 1];
        const float* hnb = shn[ci & 1];

        #pragma unroll 2
        for (int kk = 0; kk < CHUNK; kk++) {
            const ulonglong2* cp2 = (const ulonglong2*)(rowbase + kk * C_DIM);
            // 4 independent accumulator chains (depth 8 each)
            u64 a0 = pk2(-hnb[kk], 0.0f);  // fold -0.5||e||^2
            u64 a1 = pk2(0.0f, 0.0f);
            u64 a2 = a1, a3 = a1;
            #pragma unroll
            for (int j = 0; j < 16; j += 2) {
                ulonglong2 v0 = cp2[j];                    // broadcast LDS.128
                ulonglong2 v1 = cp2[j + 1];
                a0 = ffma2(tok[2 * j],     v0.x, a0);
                a1 = ffma2(tok[2 * j + 1], v0.y, a1);
                a2 = ffma2(tok[2 * j + 2], v1.x, a2);
                a3 = ffma2(tok[2 * j + 3], v1.y, a3);
            }
            float s0, s1, s2, s3, s4, s5, s6, s7;
            upk2(a0, s0, s1);
            upk2(a1, s2, s3);
            upk2(a2, s4, s5);
            upk2(a3, s6, s7);
            float s = ((s0 + s1) + (s2 + s3)) + ((s4 + s5) + (s6 + s7));
            int kidx = kbase + ci * CHUNK + kk;
            if (s > best) { best = s; bi = kidx; }         // strict > => first argmax
        }
        __syncthreads();
    }

    // sortable key: minimize over (-score, index)
    u32 u = __float_as_uint(best);
    u32 m = (best < 0.0f) ? ~u : (u | 0x80000000u);  // monotone increasing map
    u64 key = ((u64)(~m) << 32) | (u32)bi;           // larger score -> smaller key
    atomicMin(&g_key[t], key);
}

// ---------------------------------------------------------------------------
// epilogue: indices, z_q, z_q_st, counts, dw
__global__ __launch_bounds__(TPB)
void k_epi(const float* __restrict__ z, const float* __restrict__ emb,
           float* __restrict__ out) {
    const int tid = threadIdx.x;
    const int t = blockIdx.x * TPB + tid;
    const int b = t >> 10;
    const int hw = t & 1023;
    const float* zp = z + (size_t)b * (C_DIM * HW) + hw;

    int bi = (int)(u32)(g_key[t] & 0xFFFFFFFFULL);

    out[O_IDX + t] = (float)bi;
    atomicAdd(&g_counts[bi], 1.0f);

    const float4* er = (const float4*)(emb + (size_t)bi * C_DIM);
    float* dwp = g_dw + (size_t)bi * C_DIM;
    float* zq   = out + O_ZQ   + (size_t)b * (C_DIM * HW) + hw;
    float* zqst = out + O_ZQST + (size_t)b * (C_DIM * HW) + hw;

    #pragma unroll
    for (int j = 0; j < 16; j++) {
        float4 q = er[j];
        int c = 4 * j;
        float x0 = zp[(c + 0) * HW];
        float x1 = zp[(c + 1) * HW];
        float x2 = zp[(c + 2) * HW];
        float x3 = zp[(c + 3) * HW];
        zq[(c + 0) * HW] = q.x;
        zq[(c + 1) * HW] = q.y;
        zq[(c + 2) * HW] = q.z;
        zq[(c + 3) * HW] = q.w;
        zqst[(c + 0) * HW] = x0 + (q.x - x0);
        zqst[(c + 1) * HW] = x1 + (q.y - x1);
        zqst[(c + 2) * HW] = x2 + (q.z - x2);
        zqst[(c + 3) * HW] = x3 + (q.w - x3);
        atomicAdd(dwp + c + 0, x0);
        atomicAdd(dwp + c + 1, x1);
        atomicAdd(dwp + c + 2, x2);
        atomicAdd(dwp + c + 3, x3);
    }
}

// ---------------------------------------------------------------------------
// new_cluster_size + total n (single block)
__global__ void k_cs(const float* __restrict__ cs, float* __restrict__ out) {
    const float OMD = (float)(1.0 - 0.99);
    int tid = threadIdx.x;
    float loc = 0.0f;
    for (int k = tid; k < K_CODES; k += 1024) {
        float v = 0.99f * cs[k] + OMD * g_counts[k];
        out[O_CS + k] = v;
        loc += v;
    }
    __shared__ float red[32];
    #pragma unroll
    for (int o = 16; o > 0; o >>= 1) loc += __shfl_xor_sync(0xffffffffu, loc, o);
    if ((tid & 31) == 0) red[tid >> 5] = loc;
    __syncthreads();
    if (tid < 32) {
        float v = red[tid];
        #pragma unroll
        for (int o = 16; o > 0; o >>= 1) v += __shfl_xor_sync(0xffffffffu, v, o);
        if (tid == 0) g_n = v;
    }
}

// new_embedding_avg + new_embedding
__global__ void k_emb(const float* __restrict__ cs, const float* __restrict__ avg,
                      float* __restrict__ out) {
    const float OMD = (float)(1.0 - 0.99);
    const float EPSF = 1e-5f;
    int i = blockIdx.x * blockDim.x + threadIdx.x;
    if (i >= K_CODES * C_DIM) return;
    int k = i >> 6;
    float ncs = 0.99f * cs[k] + OMD * g_counts[k];
    float navg = 0.99f * avg[i] + OMD * g_dw[i];
    float n = g_n;
    float denom = (ncs + EPSF) / (n + (float)K_CODES * EPSF) * n;
    out[O_EMB + i] = navg / denom;
    out[O_AVG + i] = navg;
}

// ---------------------------------------------------------------------------
extern "C" void kernel_launch(void* const* d_in, const int* in_sizes, int n_in,
                              void* d_out, int out_size) {
    const float* z    = (const float*)d_in[0];  // z_e [16,64,32,32]
    const float* emb  = (const float*)d_in[1];  // embedding [8192,64]
    const float* cs   = (const float*)d_in[2];  // cluster_size [8192]
    const float* avg  = (const float*)d_in[3];  // embedding_avg [8192,64]
    float* out = (float*)d_out;

    k_init<<<(K_CODES * C_DIM + 255) / 256, 256>>>();
    k_hn<<<(K_CODES * 32 + 255) / 256, 256>>>(emb);
    k_dist<<<dim3(N_TOK / TPB, KSPLIT), TPB>>>(z, emb);
    k_epi<<<N_TOK / TPB, TPB>>>(z, emb, out);
    k_cs<<<1, 1024>>>(cs, out);
    k_emb<<<(K_CODES * C_DIM + 255) / 256, 256>>>(cs, avg, out);
}

// round 5
// speedup vs baseline: 1.7036x; 1.2683x over previous
#include <cuda_runtime.h>
#include <cuda_bf16.h>
#include <cstdint>

#define K_CODES 8192
#define C_DIM   64
#define N_TOK   16384
#define HW      1024
#define TPB     256
#define MTILE   128                  // tokens per CTA
#define NTILE   64                   // codes per tile
#define NTILES  (K_CODES / NTILE)    // 128

// output layout (float32, concatenated in reference return order)
#define O_ZQST 0
#define O_IDX  1048576
#define O_ZQ   1064960
#define O_EMB  2113536
#define O_CS   2637824
#define O_AVG  2646016

// smem layout for k_dist
#define SM_A    0                        // 3 comps x 128 rows x 128B = 49152
#define SM_B    49152                    // 2 bufs x 3 comps x 64 rows x 128B = 49152
#define SM_HN   98304                    // 2 x 256B
#define SMEM_TOTAL (98304 + 512)

typedef unsigned long long u64;
typedef unsigned int u32;

static __device__ __nv_bfloat16 g_Eh[K_CODES * C_DIM];
static __device__ __nv_bfloat16 g_Em[K_CODES * C_DIM];
static __device__ __nv_bfloat16 g_El[K_CODES * C_DIM];
static __device__ float g_hn[K_CODES];
static __device__ int   g_idx[N_TOK];
static __device__ float g_counts[K_CODES];
static __device__ float g_dw[K_CODES * C_DIM];
static __device__ float g_n;

// ---------------------------------------------------------------- helpers
__device__ __forceinline__ uint32_t smem_u32(const void* p) {
    uint32_t a;
    asm("{ .reg .u64 t; cvta.to.shared.u64 t, %1; cvt.u32.u64 %0, t; }"
        : "=r"(a) : "l"(p));
    return a;
}
__device__ __forceinline__ void cp_async16(uint32_t saddr, const void* gmem) {
    asm volatile("cp.async.cg.shared.global [%0], [%1], 16;\n" :: "r"(saddr), "l"(gmem));
}
#define CP_COMMIT() asm volatile("cp.async.commit_group;\n" ::: "memory")
#define CP_WAIT(n)  asm volatile("cp.async.wait_group %0;\n" :: "n"(n) : "memory")

__device__ __forceinline__ uint32_t sw128(uint32_t off) {
    return off ^ ((off >> 3) & 0x70);
}
__device__ __forceinline__ void ldsm4(u32& r0, u32& r1, u32& r2, u32& r3, uint32_t addr) {
    asm volatile("ldmatrix.sync.aligned.m8n8.x4.shared.b16 {%0,%1,%2,%3}, [%4];"
                 : "=r"(r0), "=r"(r1), "=r"(r2), "=r"(r3) : "r"(addr));
}
__device__ __forceinline__ void mma16816(float& d0, float& d1, float& d2, float& d3,
                                         u32 a0, u32 a1, u32 a2, u32 a3,
                                         u32 b0, u32 b1) {
    asm volatile("mma.sync.aligned.m16n8k16.row.col.f32.bf16.bf16.f32 "
                 "{%0,%1,%2,%3}, {%4,%5,%6,%7}, {%8,%9}, {%0,%1,%2,%3};"
                 : "+f"(d0), "+f"(d1), "+f"(d2), "+f"(d3)
                 : "r"(a0), "r"(a1), "r"(a2), "r"(a3), "r"(b0), "r"(b1));
}

// ---------------------------------------------------------------------------
__global__ void k_init() {
    int i = blockIdx.x * blockDim.x + threadIdx.x;
    if (i < K_CODES) g_counts[i] = 0.0f;
    if (i < K_CODES * C_DIM) g_dw[i] = 0.0f;
}

// split embedding into 3 bf16 components + half squared norms
__global__ void k_splitE(const float* __restrict__ emb) {
    int w = (blockIdx.x * blockDim.x + threadIdx.x) >> 5;
    int lane = threadIdx.x & 31;
    if (w >= K_CODES) return;
    float s = 0.0f;
    #pragma unroll
    for (int half = 0; half < 2; half++) {
        int c = lane + half * 32;
        float x = emb[w * C_DIM + c];
        s += x * x;
        __nv_bfloat16 h = __float2bfloat16(x);  float r = x - __bfloat162float(h);
        __nv_bfloat16 m = __float2bfloat16(r);  r -= __bfloat162float(m);
        __nv_bfloat16 l = __float2bfloat16(r);
        g_Eh[w * C_DIM + c] = h;
        g_Em[w * C_DIM + c] = m;
        g_El[w * C_DIM + c] = l;
    }
    #pragma unroll
    for (int o = 16; o > 0; o >>= 1) s += __shfl_xor_sync(0xffffffffu, s, o);
    if (lane == 0) g_hn[w] = 0.5f * s;
}

// ---------------------------------------------------------------------------
// S[t][k] = x_t . e_k via 6-term bf16 split, warp mma.sync; fused argmax.
__global__ void __launch_bounds__(TPB, 1) k_dist(const float* __restrict__ z) {
    extern __shared__ char smem[];
    const uint32_t sb = smem_u32(smem);
    const int tid = threadIdx.x;
    const int lane = tid & 31;
    const int w = tid >> 5;

    // --- load 128 tokens, exact 3-way bf16 split into sA (SW128 rows) ---
    {
        int r = tid & 127;            // token row in tile
        int half = tid >> 7;          // dims 0-31 / 32-63
        int t = blockIdx.x * MTILE + r;
        const float* zp = z + (size_t)(t >> 10) * (C_DIM * HW) + (t & 1023);
        #pragma unroll
        for (int j = 0; j < 32; j++) {
            int c = half * 32 + j;
            float x = zp[c * HW];
            __nv_bfloat16 h = __float2bfloat16(x);  float r1 = x - __bfloat162float(h);
            __nv_bfloat16 m = __float2bfloat16(r1); float r2 = r1 - __bfloat162float(m);
            __nv_bfloat16 l = __float2bfloat16(r2);
            uint32_t off = sw128((uint32_t)(r * 128 + c * 2));
            *(__nv_bfloat16*)(smem + SM_A + off) = h;
            *(__nv_bfloat16*)(smem + SM_A + 16384 + off) = m;
            *(__nv_bfloat16*)(smem + SM_A + 32768 + off) = l;
        }
    }
    __syncthreads();

    // --- preload A fragments: 3 comps x 4 ksteps x (m16k16 = 4 regs) ---
    u32 afr[3][4][4];
    {
        int arow = w * 16 + (lane & 7) + ((lane >> 3) & 1) * 8;
        int akb  = (lane >> 4) * 16;
        #pragma unroll
        for (int c = 0; c < 3; c++)
            #pragma unroll
            for (int q = 0; q < 4; q++) {
                uint32_t addr = sb + SM_A + c * 16384 +
                                sw128((uint32_t)(arow * 128 + q * 32 + akb));
                ldsm4(afr[c][q][0], afr[c][q][1], afr[c][q][2], afr[c][q][3], addr);
            }
    }

    // --- tile loader (3 comps + hn) ---
    auto load_tile = [&](int tile, int bufi) {
        const char* srcs[3] = {(const char*)g_Eh, (const char*)g_Em, (const char*)g_El};
        #pragma unroll
        for (int c = 0; c < 3; c++) {
            const char* src = srcs[c] + (size_t)tile * (NTILE * C_DIM * 2);
            uint32_t dst = sb + SM_B + (uint32_t)(bufi * 3 + c) * 8192u;
            #pragma unroll
            for (int u = 0; u < 2; u++) {
                uint32_t off = (uint32_t)(u * TPB + tid) * 16u;
                cp_async16(dst + sw128(off), src + off);
            }
        }
        if (tid < 16)
            cp_async16(sb + SM_HN + bufi * 256 + tid * 16,
                       (const char*)(g_hn + tile * NTILE) + tid * 16);
    };

    // per-lane B ldmatrix address components
    const int brow = (lane & 7) + ((lane >> 4) & 1) * 8;   // row within n16 group
    const int bkb  = ((lane >> 3) & 1) * 16;               // 16B half of k16

    float best0 = -3.4e38f, best1 = -3.4e38f;
    int bi0 = 0, bi1 = 0;

    load_tile(0, 0); CP_COMMIT();
    load_tile(1, 1); CP_COMMIT();

    for (int ci = 0; ci < NTILES; ci++) {
        const int buf = ci & 1;
        if (ci + 1 < NTILES) { CP_WAIT(1); } else { CP_WAIT(0); }
        __syncthreads();

        float acc[8][4];
        #pragma unroll
        for (int g = 0; g < 8; g++)
            #pragma unroll
            for (int v = 0; v < 4; v++) acc[g][v] = 0.0f;

        // terms: (A,B) comp pairs: cb=0 -> A {h,m,l}; cb=1 -> A {h,m}; cb=2 -> A {h}
        #pragma unroll
        for (int cb = 0; cb < 3; cb++) {
            const int na = (cb == 0) ? 3 : (cb == 1 ? 2 : 1);
            uint32_t bbase = sb + SM_B + (uint32_t)(buf * 3 + cb) * 8192u;
            #pragma unroll
            for (int q = 0; q < 4; q++) {
                u32 bfr[8][2];
                #pragma unroll
                for (int g2 = 0; g2 < 4; g2++) {
                    uint32_t addr = bbase +
                        sw128((uint32_t)((g2 * 16 + brow) * 128 + q * 32 + bkb));
                    ldsm4(bfr[2 * g2][0], bfr[2 * g2][1],
                          bfr[2 * g2 + 1][0], bfr[2 * g2 + 1][1], addr);
                }
                #pragma unroll
                for (int ca = 0; ca < 3; ca++) {
                    if (ca < na) {
                        #pragma unroll
                        for (int g = 0; g < 8; g++)
                            mma16816(acc[g][0], acc[g][1], acc[g][2], acc[g][3],
                                     afr[ca][q][0], afr[ca][q][1],
                                     afr[ca][q][2], afr[ca][q][3],
                                     bfr[g][0], bfr[g][1]);
                    }
                }
            }
        }

        // fused argmax epilogue: score = x.e - 0.5||e||^2
        const float* hnp = (const float*)(smem + SM_HN + buf * 256);
        const int colbase = ci * NTILE + 2 * (lane & 3);
        #pragma unroll
        for (int g = 0; g < 8; g++) {
            int lc = g * 8 + 2 * (lane & 3);
            float h0 = hnp[lc], h1 = hnp[lc + 1];
            int c0 = colbase + g * 8, c1 = c0 + 1;
            float s0 = acc[g][0] - h0;
            float s1 = acc[g][1] - h1;
            float s2 = acc[g][2] - h0;
            float s3 = acc[g][3] - h1;
            if (s0 > best0) { best0 = s0; bi0 = c0; }
            if (s1 > best0) { best0 = s1; bi0 = c1; }
            if (s2 > best1) { best1 = s2; bi1 = c0; }
            if (s3 > best1) { best1 = s3; bi1 = c1; }
        }

        __syncthreads();   // all warps done reading buf
        if (ci + 2 < NTILES) { load_tile(ci + 2, buf); CP_COMMIT(); }
    }

    // reduce across the 4 lanes sharing each row (tie-break: smaller index)
    #pragma unroll
    for (int o = 1; o <= 2; o <<= 1) {
        float ob0 = __shfl_xor_sync(0xffffffffu, best0, o);
        int   oi0 = __shfl_xor_sync(0xffffffffu, bi0, o);
        if (ob0 > best0 || (ob0 == best0 && oi0 < bi0)) { best0 = ob0; bi0 = oi0; }
        float ob1 = __shfl_xor_sync(0xffffffffu, best1, o);
        int   oi1 = __shfl_xor_sync(0xffffffffu, bi1, o);
        if (ob1 > best1 || (ob1 == best1 && oi1 < bi1)) { best1 = ob1; bi1 = oi1; }
    }
    if ((lane & 3) == 0) {
        int r = w * 16 + (lane >> 2);
        g_idx[blockIdx.x * MTILE + r] = bi0;
        g_idx[blockIdx.x * MTILE + r + 8] = bi1;
    }
}

// ---------------------------------------------------------------------------
// epilogue: indices, z_q, z_q_st, counts, dw  (2 threads per token)
__global__ __launch_bounds__(256)
void k_epi(const float* __restrict__ z, const float* __restrict__ emb,
           float* __restrict__ out) {
    const int gid = blockIdx.x * blockDim.x + threadIdx.x;
    const int t = gid >> 1;
    const int half = gid & 1;
    if (t >= N_TOK) return;
    const int b = t >> 10;
    const int hw = t & 1023;
    const float* zp = z + (size_t)b * (C_DIM * HW) + hw;

    int bi = g_idx[t];
    if (half == 0) {
        out[O_IDX + t] = (float)bi;
        atomicAdd(&g_counts[bi], 1.0f);
    }

    const float4* er = (const float4*)(emb + (size_t)bi * C_DIM) + half * 8;
    float* dwp = g_dw + (size_t)bi * C_DIM;
    float* zq   = out + O_ZQ   + (size_t)b * (C_DIM * HW) + hw;
    float* zqst = out + O_ZQST + (size_t)b * (C_DIM * HW) + hw;

    #pragma unroll
    for (int j = 0; j < 8; j++) {
        float4 q = er[j];
        int c = half * 32 + 4 * j;
        float x0 = zp[(c + 0) * HW];
        float x1 = zp[(c + 1) * HW];
        float x2 = zp[(c + 2) * HW];
        float x3 = zp[(c + 3) * HW];
        zq[(c + 0) * HW] = q.x;
        zq[(c + 1) * HW] = q.y;
        zq[(c + 2) * HW] = q.z;
        zq[(c + 3) * HW] = q.w;
        zqst[(c + 0) * HW] = x0 + (q.x - x0);
        zqst[(c + 1) * HW] = x1 + (q.y - x1);
        zqst[(c + 2) * HW] = x2 + (q.z - x2);
        zqst[(c + 3) * HW] = x3 + (q.w - x3);
        atomicAdd(dwp + c + 0, x0);
        atomicAdd(dwp + c + 1, x1);
        atomicAdd(dwp + c + 2, x2);
        atomicAdd(dwp + c + 3, x3);
    }
}

// ---------------------------------------------------------------------------
__global__ void k_cs(const float* __restrict__ cs, float* __restrict__ out) {
    const float OMD = 0.01f;
    int tid = threadIdx.x;
    float loc = 0.0f;
    for (int k = tid; k < K_CODES; k += 1024) {
        float v = 0.99f * cs[k] + OMD * g_counts[k];
        out[O_CS + k] = v;
        loc += v;
    }
    __shared__ float red[32];
    #pragma unroll
    for (int o = 16; o > 0; o >>= 1) loc += __shfl_xor_sync(0xffffffffu, loc, o);
    if ((tid & 31) == 0) red[tid >> 5] = loc;
    __syncthreads();
    if (tid < 32) {
        float v = red[tid];
        #pragma unroll
        for (int o = 16; o > 0; o >>= 1) v += __shfl_xor_sync(0xffffffffu, v, o);
        if (tid == 0) g_n = v;
    }
}

__global__ void k_emb(const float* __restrict__ cs, const float* __restrict__ avg,
                      float* __restrict__ out) {
    const float OMD = 0.01f;
    const float EPSF = 1e-5f;
    int i = blockIdx.x * blockDim.x + threadIdx.x;
    if (i >= K_CODES * C_DIM) return;
    int k = i >> 6;
    float ncs = 0.99f * cs[k] + OMD * g_counts[k];
    float navg = 0.99f * avg[i] + OMD * g_dw[i];
    float n = g_n;
    float denom = (ncs + EPSF) / (n + (float)K_CODES * EPSF) * n;
    out[O_EMB + i] = navg / denom;
    out[O_AVG + i] = navg;
}

// ---------------------------------------------------------------------------
extern "C" void kernel_launch(void* const* d_in, const int* in_sizes, int n_in,
                              void* d_out, int out_size) {
    const float* z   = (const float*)d_in[0];
    const float* emb = (const float*)d_in[1];
    const float* cs  = (const float*)d_in[2];
    const float* avg = (const float*)d_in[3];
    float* out = (float*)d_out;

    cudaFuncSetAttribute(k_dist, cudaFuncAttributeMaxDynamicSharedMemorySize, SMEM_TOTAL);

    k_init<<<(K_CODES * C_DIM + 255) / 256, 256>>>();
    k_splitE<<<(K_CODES * 32 + 255) / 256, 256>>>(emb);
    k_dist<<<N_TOK / MTILE, TPB, SMEM_TOTAL>>>(z);
    k_epi<<<(2 * N_TOK + 255) / 256, 256>>>(z, emb, out);
    k_cs<<<1, 1024>>>(cs, out);
    k_emb<<<(K_CODES * C_DIM + 255) / 256, 256>>>(cs, avg, out);
}

// round 6
// speedup vs baseline: 2.0459x; 1.2009x over previous
#include <cuda_runtime.h>
#include <cuda_fp16.h>
#include <cstdint>

#define K_CODES 8192
#define C_DIM   64
#define N_TOK   16384
#define HW      1024
#define TPB     256
#define MTILE   128                  // tokens per CTA
#define NTILE   64                   // codes per tile
#define NTILES  (K_CODES / NTILE)    // 128
#define MARGIN  1e-3f

// output layout (float32, concatenated in reference return order)
#define O_ZQST 0
#define O_IDX  1048576
#define O_ZQ   1064960
#define O_EMB  2113536
#define O_CS   2637824
#define O_AVG  2646016

// smem layout for k_dist
#define SM_A    0                        // 2 comps x 128 rows x 128B = 32768
#define SM_B    32768                    // 2 bufs x 2 comps x 64 rows x 128B = 32768
#define SM_HN   65536                    // 2 x 256B
#define SMEM_TOTAL (65536 + 512 + 128)

typedef unsigned long long u64;
typedef unsigned int u32;

static __device__ __half g_Eh[K_CODES * C_DIM];
static __device__ __half g_Er[K_CODES * C_DIM];
static __device__ float g_hn[K_CODES];
static __device__ int   g_idx[N_TOK];
static __device__ int   g_flag[N_TOK];
static __device__ float g_counts[K_CODES];
static __device__ float g_dw[K_CODES * C_DIM];
static __device__ float g_n;

// ---------------------------------------------------------------- helpers
__device__ __forceinline__ uint32_t smem_u32(const void* p) {
    uint32_t a;
    asm("{ .reg .u64 t; cvta.to.shared.u64 t, %1; cvt.u32.u64 %0, t; }"
        : "=r"(a) : "l"(p));
    return a;
}
__device__ __forceinline__ void cp_async16(uint32_t saddr, const void* gmem) {
    asm volatile("cp.async.cg.shared.global [%0], [%1], 16;\n" :: "r"(saddr), "l"(gmem));
}
#define CP_COMMIT() asm volatile("cp.async.commit_group;\n" ::: "memory")
#define CP_WAIT(n)  asm volatile("cp.async.wait_group %0;\n" :: "n"(n) : "memory")

__device__ __forceinline__ uint32_t sw128(uint32_t off) {
    return off ^ ((off >> 3) & 0x70);
}
__device__ __forceinline__ void ldsm4(u32& r0, u32& r1, u32& r2, u32& r3, uint32_t addr) {
    asm volatile("ldmatrix.sync.aligned.m8n8.x4.shared.b16 {%0,%1,%2,%3}, [%4];"
                 : "=r"(r0), "=r"(r1), "=r"(r2), "=r"(r3) : "r"(addr));
}
__device__ __forceinline__ void mma16816(float& d0, float& d1, float& d2, float& d3,
                                         u32 a0, u32 a1, u32 a2, u32 a3,
                                         u32 b0, u32 b1) {
    asm volatile("mma.sync.aligned.m16n8k16.row.col.f32.f16.f16.f32 "
                 "{%0,%1,%2,%3}, {%4,%5,%6,%7}, {%8,%9}, {%0,%1,%2,%3};"
                 : "+f"(d0), "+f"(d1), "+f"(d2), "+f"(d3)
                 : "r"(a0), "r"(a1), "r"(a2), "r"(a3), "r"(b0), "r"(b1));
}

// ---------------------------------------------------------------------------
__global__ void k_init() {
    int i = blockIdx.x * blockDim.x + threadIdx.x;
    if (i < K_CODES) g_counts[i] = 0.0f;
    if (i < K_CODES * C_DIM) g_dw[i] = 0.0f;
}

// split embedding into 2 fp16 components + half squared norms
__global__ void k_splitE(const float* __restrict__ emb) {
    int w = (blockIdx.x * blockDim.x + threadIdx.x) >> 5;
    int lane = threadIdx.x & 31;
    if (w >= K_CODES) return;
    float s = 0.0f;
    #pragma unroll
    for (int half = 0; half < 2; half++) {
        int c = lane + half * 32;
        float x = emb[w * C_DIM + c];
        s += x * x;
        __half h = __float2half_rn(x);
        float r = x - __half2float(h);
        g_Eh[w * C_DIM + c] = h;
        g_Er[w * C_DIM + c] = __float2half_rn(r);
    }
    #pragma unroll
    for (int o = 16; o > 0; o >>= 1) s += __shfl_xor_sync(0xffffffffu, s, o);
    if (lane == 0) g_hn[w] = 0.5f * s;
}

// ---------------------------------------------------------------------------
// S[t][k] = x_t . e_k via 3-term fp16 split, warp mma.sync; fused argmax+top2.
__global__ void __launch_bounds__(TPB, 1) k_dist(const float* __restrict__ z) {
    extern __shared__ char smem[];
    const uint32_t sb = smem_u32(smem);
    const int tid = threadIdx.x;
    const int lane = tid & 31;
    const int w = tid >> 5;

    // --- load 128 tokens, 2-way fp16 split into sA (SW128 rows) ---
    {
        int r = tid & 127;            // token row in tile
        int half = tid >> 7;          // dims 0-31 / 32-63
        int t = blockIdx.x * MTILE + r;
        const float* zp = z + (size_t)(t >> 10) * (C_DIM * HW) + (t & 1023);
        #pragma unroll
        for (int j = 0; j < 32; j++) {
            int c = half * 32 + j;
            float x = zp[c * HW];
            __half h = __float2half_rn(x);
            float rr = x - __half2float(h);
            uint32_t off = sw128((uint32_t)(r * 128 + c * 2));
            *(__half*)(smem + SM_A + off) = h;
            *(__half*)(smem + SM_A + 16384 + off) = __float2half_rn(rr);
        }
    }
    __syncthreads();

    // --- preload A fragments: 2 comps x 4 ksteps x (m16k16 = 4 regs) ---
    u32 afr[2][4][4];
    {
        int arow = w * 16 + (lane & 7) + ((lane >> 3) & 1) * 8;
        int akb  = (lane >> 4) * 16;
        #pragma unroll
        for (int c = 0; c < 2; c++)
            #pragma unroll
            for (int q = 0; q < 4; q++) {
                uint32_t addr = sb + SM_A + c * 16384 +
                                sw128((uint32_t)(arow * 128 + q * 32 + akb));
                ldsm4(afr[c][q][0], afr[c][q][1], afr[c][q][2], afr[c][q][3], addr);
            }
    }

    // --- tile loader (2 comps + hn) ---
    auto load_tile = [&](int tile, int bufi) {
        const char* srcs[2] = {(const char*)g_Eh, (const char*)g_Er};
        #pragma unroll
        for (int c = 0; c < 2; c++) {
            const char* src = srcs[c] + (size_t)tile * (NTILE * C_DIM * 2);
            uint32_t dst = sb + SM_B + (uint32_t)(bufi * 2 + c) * 8192u;
            #pragma unroll
            for (int u = 0; u < 2; u++) {
                uint32_t off = (uint32_t)(u * TPB + tid) * 16u;
                cp_async16(dst + sw128(off), src + off);
            }
        }
        if (tid < 16)
            cp_async16(sb + SM_HN + bufi * 256 + tid * 16,
                       (const char*)(g_hn + tile * NTILE) + tid * 16);
    };

    // per-lane B ldmatrix address components
    const int brow = (lane & 7) + ((lane >> 4) & 1) * 8;
    const int bkb  = ((lane >> 3) & 1) * 16;

    // per-lane top-2 for each of the two token rows this lane touches
    float b1_0 = -3.4e38f, b2_0 = -3.4e38f;
    float b1_1 = -3.4e38f, b2_1 = -3.4e38f;
    int i1_0 = 0, i1_1 = 0;

    load_tile(0, 0); CP_COMMIT();
    load_tile(1, 1); CP_COMMIT();

    for (int ci = 0; ci < NTILES; ci++) {
        const int buf = ci & 1;
        if (ci + 1 < NTILES) { CP_WAIT(1); } else { CP_WAIT(0); }
        __syncthreads();

        float acc[8][4];
        #pragma unroll
        for (int g = 0; g < 8; g++)
            #pragma unroll
            for (int v = 0; v < 4; v++) acc[g][v] = 0.0f;

        #pragma unroll
        for (int q = 0; q < 4; q++) {
            u32 bfr[8][2];
            // B comp 0 (h_e): terms hh (A0) and rh (A1)
            uint32_t b0base = sb + SM_B + (uint32_t)(buf * 2) * 8192u;
            #pragma unroll
            for (int g2 = 0; g2 < 4; g2++) {
                uint32_t addr = b0base +
                    sw128((uint32_t)((g2 * 16 + brow) * 128 + q * 32 + bkb));
                ldsm4(bfr[2 * g2][0], bfr[2 * g2][1],
                      bfr[2 * g2 + 1][0], bfr[2 * g2 + 1][1], addr);
            }
            #pragma unroll
            for (int g = 0; g < 8; g++) {
                mma16816(acc[g][0], acc[g][1], acc[g][2], acc[g][3],
                         afr[0][q][0], afr[0][q][1], afr[0][q][2], afr[0][q][3],
                         bfr[g][0], bfr[g][1]);
                mma16816(acc[g][0], acc[g][1], acc[g][2], acc[g][3],
                         afr[1][q][0], afr[1][q][1], afr[1][q][2], afr[1][q][3],
                         bfr[g][0], bfr[g][1]);
            }
            // B comp 1 (r_e): term hr (A0)
            uint32_t b1base = sb + SM_B + (uint32_t)(buf * 2 + 1) * 8192u;
            #pragma unroll
            for (int g2 = 0; g2 < 4; g2++) {
                uint32_t addr = b1base +
                    sw128((uint32_t)((g2 * 16 + brow) * 128 + q * 32 + bkb));
                ldsm4(bfr[2 * g2][0], bfr[2 * g2][1],
                      bfr[2 * g2 + 1][0], bfr[2 * g2 + 1][1], addr);
            }
            #pragma unroll
            for (int g = 0; g < 8; g++)
                mma16816(acc[g][0], acc[g][1], acc[g][2], acc[g][3],
                         afr[0][q][0], afr[0][q][1], afr[0][q][2], afr[0][q][3],
                         bfr[g][0], bfr[g][1]);
        }

        // fused top-2 epilogue: score = x.e - 0.5||e||^2
        const float* hnp = (const float*)(smem + SM_HN + buf * 256);
        const int colbase = ci * NTILE + 2 * (lane & 3);
        #pragma unroll
        for (int g = 0; g < 8; g++) {
            int lc = g * 8 + 2 * (lane & 3);
            float h0 = hnp[lc], h1 = hnp[lc + 1];
            int c0 = colbase + g * 8, c1 = c0 + 1;
            float s0 = acc[g][0] - h0;
            float s1 = acc[g][1] - h1;
            float s2 = acc[g][2] - h0;
            float s3 = acc[g][3] - h1;
            if (s0 > b1_0) { b2_0 = b1_0; b1_0 = s0; i1_0 = c0; }
            else if (s0 > b2_0) b2_0 = s0;
            if (s1 > b1_0) { b2_0 = b1_0; b1_0 = s1; i1_0 = c1; }
            else if (s1 > b2_0) b2_0 = s1;
            if (s2 > b1_1) { b2_1 = b1_1; b1_1 = s2; i1_1 = c0; }
            else if (s2 > b2_1) b2_1 = s2;
            if (s3 > b1_1) { b2_1 = b1_1; b1_1 = s3; i1_1 = c1; }
            else if (s3 > b2_1) b2_1 = s3;
        }

        __syncthreads();   // all warps done reading buf
        if (ci + 2 < NTILES) { load_tile(ci + 2, buf); CP_COMMIT(); }
    }

    // merge top-2 across the 4 lanes sharing each row
    #pragma unroll
    for (int o = 1; o <= 2; o <<= 1) {
        float ob1 = __shfl_xor_sync(0xffffffffu, b1_0, o);
        float ob2 = __shfl_xor_sync(0xffffffffu, b2_0, o);
        int   oi1 = __shfl_xor_sync(0xffffffffu, i1_0, o);
        if (ob1 > b1_0 || (ob1 == b1_0 && oi1 < i1_0)) {
            b2_0 = fmaxf(b1_0, ob2); b1_0 = ob1; i1_0 = oi1;
        } else {
            b2_0 = fmaxf(b2_0, ob1);
        }
        ob1 = __shfl_xor_sync(0xffffffffu, b1_1, o);
        ob2 = __shfl_xor_sync(0xffffffffu, b2_1, o);
        oi1 = __shfl_xor_sync(0xffffffffu, i1_1, o);
        if (ob1 > b1_1 || (ob1 == b1_1 && oi1 < i1_1)) {
            b2_1 = fmaxf(b1_1, ob2); b1_1 = ob1; i1_1 = oi1;
        } else {
            b2_1 = fmaxf(b2_1, ob1);
        }
    }
    if ((lane & 3) == 0) {
        int r = w * 16 + (lane >> 2);
        int t0 = blockIdx.x * MTILE + r;
        g_idx[t0] = i1_0;
        g_flag[t0] = (b1_0 - b2_0 < MARGIN) ? 1 : 0;
        g_idx[t0 + 8] = i1_1;
        g_flag[t0 + 8] = (b1_1 - b2_1 < MARGIN) ? 1 : 0;
    }
}

// ---------------------------------------------------------------------------
// exact fp32 re-argmax for flagged (ambiguous) tokens: one warp per token
__global__ __launch_bounds__(256)
void k_refine(const float* __restrict__ z, const float* __restrict__ emb) {
    __shared__ float sx[8][C_DIM];
    const int lane = threadIdx.x & 31;
    const int wl = threadIdx.x >> 5;
    const int t = blockIdx.x * 8 + wl;
    if (g_flag[t] == 0) return;

    const float* zp = z + (size_t)(t >> 10) * (C_DIM * HW) + (t & 1023);
    sx[wl][lane] = zp[lane * HW];
    sx[wl][lane + 32] = zp[(lane + 32) * HW];
    __syncwarp();

    float best = -3.4e38f;
    int bidx = K_CODES;
    for (int k = lane; k < K_CODES; k += 32) {
        const float4* e4 = (const float4*)(emb + (size_t)k * C_DIM);
        float s = 0.0f;
        #pragma unroll
        for (int j = 0; j < 16; j++) {
            float4 e = e4[j];
            s += sx[wl][4 * j] * e.x + sx[wl][4 * j + 1] * e.y
               + sx[wl][4 * j + 2] * e.z + sx[wl][4 * j + 3] * e.w;
        }
        s -= g_hn[k];
        if (s > best || (s == best && k < bidx)) { best = s; bidx = k; }
    }
    #pragma unroll
    for (int o = 16; o > 0; o >>= 1) {
        float ob = __shfl_xor_sync(0xffffffffu, best, o);
        int   oi = __shfl_xor_sync(0xffffffffu, bidx, o);
        if (ob > best || (ob == best && oi < bidx)) { best = ob; bidx = oi; }
    }
    if (lane == 0) g_idx[t] = bidx;
}

// ---------------------------------------------------------------------------
// epilogue: indices, z_q, z_q_st, counts, dw  (4 threads per token)
__global__ __launch_bounds__(256)
void k_epi(const float* __restrict__ z, const float* __restrict__ emb,
           float* __restrict__ out) {
    const int gid = blockIdx.x * blockDim.x + threadIdx.x;
    const int t = gid >> 2;
    const int part = gid & 3;
    if (t >= N_TOK) return;
    const int b = t >> 10;
    const int hw = t & 1023;
    const float* zp = z + (size_t)b * (C_DIM * HW) + hw;

    int bi = g_idx[t];
    if (part == 0) {
        out[O_IDX + t] = (float)bi;
        atomicAdd(&g_counts[bi], 1.0f);
    }

    const float4* er = (const float4*)(emb + (size_t)bi * C_DIM) + part * 4;
    float* dwp = g_dw + (size_t)bi * C_DIM;
    float* zq   = out + O_ZQ   + (size_t)b * (C_DIM * HW) + hw;
    float* zqst = out + O_ZQST + (size_t)b * (C_DIM * HW) + hw;

    #pragma unroll
    for (int j = 0; j < 4; j++) {
        float4 q = er[j];
        int c = part * 16 + 4 * j;
        float x0 = zp[(c + 0) * HW];
        float x1 = zp[(c + 1) * HW];
        float x2 = zp[(c + 2) * HW];
        float x3 = zp[(c + 3) * HW];
        zq[(c + 0) * HW] = q.x;
        zq[(c + 1) * HW] = q.y;
        zq[(c + 2) * HW] = q.z;
        zq[(c + 3) * HW] = q.w;
        zqst[(c + 0) * HW] = x0 + (q.x - x0);
        zqst[(c + 1) * HW] = x1 + (q.y - x1);
        zqst[(c + 2) * HW] = x2 + (q.z - x2);
        zqst[(c + 3) * HW] = x3 + (q.w - x3);
        atomicAdd(dwp + c + 0, x0);
        atomicAdd(dwp + c + 1, x1);
        atomicAdd(dwp + c + 2, x2);
        atomicAdd(dwp + c + 3, x3);
    }
}

// ---------------------------------------------------------------------------
__global__ void k_cs(const float* __restrict__ cs, float* __restrict__ out) {
    const float OMD = 0.01f;
    int tid = threadIdx.x;
    float loc = 0.0f;
    for (int k = tid; k < K_CODES; k += 1024) {
        float v = 0.99f * cs[k] + OMD * g_counts[k];
        out[O_CS + k] = v;
        loc += v;
    }
    __shared__ float red[32];
    #pragma unroll
    for (int o = 16; o > 0; o >>= 1) loc += __shfl_xor_sync(0xffffffffu, loc, o);
    if ((tid & 31) == 0) red[tid >> 5] = loc;
    __syncthreads();
    if (tid < 32) {
        float v = red[tid];
        #pragma unroll
        for (int o = 16; o > 0; o >>= 1) v += __shfl_xor_sync(0xffffffffu, v, o);
        if (tid == 0) g_n = v;
    }
}

__global__ void k_emb(const float* __restrict__ cs, const float* __restrict__ avg,
                      float* __restrict__ out) {
    const float OMD = 0.01f;
    const float EPSF = 1e-5f;
    int i = blockIdx.x * blockDim.x + threadIdx.x;
    if (i >= K_CODES * C_DIM) return;
    int k = i >> 6;
    float ncs = 0.99f * cs[k] + OMD * g_counts[k];
    float navg = 0.99f * avg[i] + OMD * g_dw[i];
    float n = g_n;
    float denom = (ncs + EPSF) / (n + (float)K_CODES * EPSF) * n;
    out[O_EMB + i] = navg / denom;
    out[O_AVG + i] = navg;
}

// ---------------------------------------------------------------------------
extern "C" void kernel_launch(void* const* d_in, const int* in_sizes, int n_in,
                              void* d_out, int out_size) {
    const float* z   = (const float*)d_in[0];
    const float* emb = (const float*)d_in[1];
    const float* cs  = (const float*)d_in[2];
    const float* avg = (const float*)d_in[3];
    float* out = (float*)d_out;

    cudaFuncSetAttribute(k_dist, cudaFuncAttributeMaxDynamicSharedMemorySize, SMEM_TOTAL);

    k_init<<<(K_CODES * C_DIM + 255) / 256, 256>>>();
    k_splitE<<<(K_CODES * 32 + 255) / 256, 256>>>(emb);
    k_dist<<<N_TOK / MTILE, TPB, SMEM_TOTAL>>>(z);
    k_refine<<<N_TOK / 8, 256>>>(z, emb);
    k_epi<<<(4 * N_TOK + 255) / 256, 256>>>(z, emb, out);
    k_cs<<<1, 1024>>>(cs, out);
    k_emb<<<(K_CODES * C_DIM + 255) / 256, 256>>>(cs, avg, out);
}

// round 7
// speedup vs baseline: 2.7866x; 1.3620x over previous
#include <cuda_runtime.h>
#include <cuda_fp16.h>
#include <cstdint>

#define K_CODES 8192
#define C_DIM   64
#define N_TOK   16384
#define HW      1024
#define TPB     256
#define MTILE   128                  // tokens per CTA
#define NTILE   64                   // codes per tile
#define NTILES  (K_CODES / NTILE)    // 128
#define MARGIN  1e-4f

// output layout (float32, concatenated in reference return order)
#define O_ZQST 0
#define O_IDX  1048576
#define O_ZQ   1064960
#define O_EMB  2113536
#define O_CS   2637824
#define O_AVG  2646016

// smem layout for k_dist
#define SM_A    0                        // 2 comps x 128 rows x 128B = 32768
#define SM_B    32768                    // 2 bufs x 2 comps x 64 rows x 128B = 32768
#define SM_HN   65536                    // 2 x 256B
#define SMEM_TOTAL (65536 + 512 + 128)

typedef unsigned long long u64;
typedef unsigned int u32;

static __device__ __half g_Eh[K_CODES * C_DIM];
static __device__ __half g_Er[K_CODES * C_DIM];
static __device__ float g_hn[K_CODES];
static __device__ int   g_idx[N_TOK];
static __device__ int   g_list[N_TOK];
static __device__ int   g_nflag;
static __device__ float g_counts[K_CODES];
static __device__ float g_dw[K_CODES * C_DIM];
static __device__ float g_n;

// ---------------------------------------------------------------- helpers
__device__ __forceinline__ uint32_t smem_u32(const void* p) {
    uint32_t a;
    asm("{ .reg .u64 t; cvta.to.shared.u64 t, %1; cvt.u32.u64 %0, t; }"
        : "=r"(a) : "l"(p));
    return a;
}
__device__ __forceinline__ void cp_async16(uint32_t saddr, const void* gmem) {
    asm volatile("cp.async.cg.shared.global [%0], [%1], 16;\n" :: "r"(saddr), "l"(gmem));
}
#define CP_COMMIT() asm volatile("cp.async.commit_group;\n" ::: "memory")
#define CP_WAIT(n)  asm volatile("cp.async.wait_group %0;\n" :: "n"(n) : "memory")

__device__ __forceinline__ uint32_t sw128(uint32_t off) {
    return off ^ ((off >> 3) & 0x70);
}
__device__ __forceinline__ void ldsm4(u32& r0, u32& r1, u32& r2, u32& r3, uint32_t addr) {
    asm volatile("ldmatrix.sync.aligned.m8n8.x4.shared.b16 {%0,%1,%2,%3}, [%4];"
                 : "=r"(r0), "=r"(r1), "=r"(r2), "=r"(r3) : "r"(addr));
}
__device__ __forceinline__ void mma16816(float& d0, float& d1, float& d2, float& d3,
                                         u32 a0, u32 a1, u32 a2, u32 a3,
                                         u32 b0, u32 b1) {
    asm volatile("mma.sync.aligned.m16n8k16.row.col.f32.f16.f16.f32 "
                 "{%0,%1,%2,%3}, {%4,%5,%6,%7}, {%8,%9}, {%0,%1,%2,%3};"
                 : "+f"(d0), "+f"(d1), "+f"(d2), "+f"(d3)
                 : "r"(a0), "r"(a1), "r"(a2), "r"(a3), "r"(b0), "r"(b1));
}

// ---------------------------------------------------------------------------
__global__ void k_init() {
    int i = blockIdx.x * blockDim.x + threadIdx.x;
    if (i < K_CODES) g_counts[i] = 0.0f;
    if (i < K_CODES * C_DIM) g_dw[i] = 0.0f;
    if (i == 0) g_nflag = 0;
}

// split embedding into 2 fp16 components + half squared norms
__global__ void k_splitE(const float* __restrict__ emb) {
    int w = (blockIdx.x * blockDim.x + threadIdx.x) >> 5;
    int lane = threadIdx.x & 31;
    if (w >= K_CODES) return;
    float s = 0.0f;
    #pragma unroll
    for (int half = 0; half < 2; half++) {
        int c = lane + half * 32;
        float x = emb[w * C_DIM + c];
        s += x * x;
        __half h = __float2half_rn(x);
        float r = x - __half2float(h);
        g_Eh[w * C_DIM + c] = h;
        g_Er[w * C_DIM + c] = __float2half_rn(r);
    }
    #pragma unroll
    for (int o = 16; o > 0; o >>= 1) s += __shfl_xor_sync(0xffffffffu, s, o);
    if (lane == 0) g_hn[w] = 0.5f * s;
}

// ---------------------------------------------------------------------------
// S[t][k] = x_t . e_k via 3-term fp16 split, warp mma.sync; fused argmax+top2.
__global__ void __launch_bounds__(TPB, 1) k_dist(const float* __restrict__ z) {
    extern __shared__ char smem[];
    const uint32_t sb = smem_u32(smem);
    const int tid = threadIdx.x;
    const int lane = tid & 31;
    const int w = tid >> 5;

    // --- load 128 tokens, 2-way fp16 split into sA (SW128 rows) ---
    {
        int r = tid & 127;            // token row in tile
        int half = tid >> 7;          // dims 0-31 / 32-63
        int t = blockIdx.x * MTILE + r;
        const float* zp = z + (size_t)(t >> 10) * (C_DIM * HW) + (t & 1023);
        #pragma unroll
        for (int j = 0; j < 32; j++) {
            int c = half * 32 + j;
            float x = zp[c * HW];
            __half h = __float2half_rn(x);
            float rr = x - __half2float(h);
            uint32_t off = sw128((uint32_t)(r * 128 + c * 2));
            *(__half*)(smem + SM_A + off) = h;
            *(__half*)(smem + SM_A + 16384 + off) = __float2half_rn(rr);
        }
    }
    __syncthreads();

    // --- preload A fragments: 2 comps x 4 ksteps x (m16k16 = 4 regs) ---
    u32 afr[2][4][4];
    {
        int arow = w * 16 + (lane & 7) + ((lane >> 3) & 1) * 8;
        int akb  = (lane >> 4) * 16;
        #pragma unroll
        for (int c = 0; c < 2; c++)
            #pragma unroll
            for (int q = 0; q < 4; q++) {
                uint32_t addr = sb + SM_A + c * 16384 +
                                sw128((uint32_t)(arow * 128 + q * 32 + akb));
                ldsm4(afr[c][q][0], afr[c][q][1], afr[c][q][2], afr[c][q][3], addr);
            }
    }

    // --- tile loader (2 comps + hn) ---
    auto load_tile = [&](int tile, int bufi) {
        const char* srcs[2] = {(const char*)g_Eh, (const char*)g_Er};
        #pragma unroll
        for (int c = 0; c < 2; c++) {
            const char* src = srcs[c] + (size_t)tile * (NTILE * C_DIM * 2);
            uint32_t dst = sb + SM_B + (uint32_t)(bufi * 2 + c) * 8192u;
            #pragma unroll
            for (int u = 0; u < 2; u++) {
                uint32_t off = (uint32_t)(u * TPB + tid) * 16u;
                cp_async16(dst + sw128(off), src + off);
            }
        }
        if (tid < 16)
            cp_async16(sb + SM_HN + bufi * 256 + tid * 16,
                       (const char*)(g_hn + tile * NTILE) + tid * 16);
    };

    // per-lane B ldmatrix address components
    const int brow = (lane & 7) + ((lane >> 4) & 1) * 8;
    const int bkb  = ((lane >> 3) & 1) * 16;

    // per-lane top-2 for each of the two token rows this lane touches
    float b1_0 = -3.4e38f, b2_0 = -3.4e38f;
    float b1_1 = -3.4e38f, b2_1 = -3.4e38f;
    int i1_0 = 0, i1_1 = 0;

    load_tile(0, 0); CP_COMMIT();
    load_tile(1, 1); CP_COMMIT();

    for (int ci = 0; ci < NTILES; ci++) {
        const int buf = ci & 1;
        if (ci + 1 < NTILES) { CP_WAIT(1); } else { CP_WAIT(0); }
        __syncthreads();

        float acc[8][4];
        #pragma unroll
        for (int g = 0; g < 8; g++)
            #pragma unroll
            for (int v = 0; v < 4; v++) acc[g][v] = 0.0f;

        #pragma unroll
        for (int q = 0; q < 4; q++) {
            u32 bfr[8][2];
            // B comp 0 (h_e): terms hh (A0) and rh (A1)
            uint32_t b0base = sb + SM_B + (uint32_t)(buf * 2) * 8192u;
            #pragma unroll
            for (int g2 = 0; g2 < 4; g2++) {
                uint32_t addr = b0base +
                    sw128((uint32_t)((g2 * 16 + brow) * 128 + q * 32 + bkb));
                ldsm4(bfr[2 * g2][0], bfr[2 * g2][1],
                      bfr[2 * g2 + 1][0], bfr[2 * g2 + 1][1], addr);
            }
            #pragma unroll
            for (int g = 0; g < 8; g++) {
                mma16816(acc[g][0], acc[g][1], acc[g][2], acc[g][3],
                         afr[0][q][0], afr[0][q][1], afr[0][q][2], afr[0][q][3],
                         bfr[g][0], bfr[g][1]);
                mma16816(acc[g][0], acc[g][1], acc[g][2], acc[g][3],
                         afr[1][q][0], afr[1][q][1], afr[1][q][2], afr[1][q][3],
                         bfr[g][0], bfr[g][1]);
            }
            // B comp 1 (r_e): term hr (A0)
            uint32_t b1base = sb + SM_B + (uint32_t)(buf * 2 + 1) * 8192u;
            #pragma unroll
            for (int g2 = 0; g2 < 4; g2++) {
                uint32_t addr = b1base +
                    sw128((uint32_t)((g2 * 16 + brow) * 128 + q * 32 + bkb));
                ldsm4(bfr[2 * g2][0], bfr[2 * g2][1],
                      bfr[2 * g2 + 1][0], bfr[2 * g2 + 1][1], addr);
            }
            #pragma unroll
            for (int g = 0; g < 8; g++)
                mma16816(acc[g][0], acc[g][1], acc[g][2], acc[g][3],
                         afr[0][q][0], afr[0][q][1], afr[0][q][2], afr[0][q][3],
                         bfr[g][0], bfr[g][1]);
        }

        // fused top-2 epilogue: score = x.e - 0.5||e||^2
        const float* hnp = (const float*)(smem + SM_HN + buf * 256);
        const int colbase = ci * NTILE + 2 * (lane & 3);
        #pragma unroll
        for (int g = 0; g < 8; g++) {
            int lc = g * 8 + 2 * (lane & 3);
            float h0 = hnp[lc], h1 = hnp[lc + 1];
            int c0 = colbase + g * 8, c1 = c0 + 1;
            float s0 = acc[g][0] - h0;
            float s1 = acc[g][1] - h1;
            float s2 = acc[g][2] - h0;
            float s3 = acc[g][3] - h1;
            if (s0 > b1_0) { b2_0 = b1_0; b1_0 = s0; i1_0 = c0; }
            else if (s0 > b2_0) b2_0 = s0;
            if (s1 > b1_0) { b2_0 = b1_0; b1_0 = s1; i1_0 = c1; }
            else if (s1 > b2_0) b2_0 = s1;
            if (s2 > b1_1) { b2_1 = b1_1; b1_1 = s2; i1_1 = c0; }
            else if (s2 > b2_1) b2_1 = s2;
            if (s3 > b1_1) { b2_1 = b1_1; b1_1 = s3; i1_1 = c1; }
            else if (s3 > b2_1) b2_1 = s3;
        }

        __syncthreads();   // all warps done reading buf
        if (ci + 2 < NTILES) { load_tile(ci + 2, buf); CP_COMMIT(); }
    }

    // merge top-2 across the 4 lanes sharing each row
    #pragma unroll
    for (int o = 1; o <= 2; o <<= 1) {
        float ob1 = __shfl_xor_sync(0xffffffffu, b1_0, o);
        float ob2 = __shfl_xor_sync(0xffffffffu, b2_0, o);
        int   oi1 = __shfl_xor_sync(0xffffffffu, i1_0, o);
        if (ob1 > b1_0 || (ob1 == b1_0 && oi1 < i1_0)) {
            b2_0 = fmaxf(b1_0, ob2); b1_0 = ob1; i1_0 = oi1;
        } else {
            b2_0 = fmaxf(b2_0, ob1);
        }
        ob1 = __shfl_xor_sync(0xffffffffu, b1_1, o);
        ob2 = __shfl_xor_sync(0xffffffffu, b2_1, o);
        oi1 = __shfl_xor_sync(0xffffffffu, i1_1, o);
        if (ob1 > b1_1 || (ob1 == b1_1 && oi1 < i1_1)) {
            b2_1 = fmaxf(b1_1, ob2); b1_1 = ob1; i1_1 = oi1;
        } else {
            b2_1 = fmaxf(b2_1, ob1);
        }
    }
    if ((lane & 3) == 0) {
        int r = w * 16 + (lane >> 2);
        int t0 = blockIdx.x * MTILE + r;
        g_idx[t0] = i1_0;
        if (b1_0 - b2_0 < MARGIN) {
            int slot = atomicAdd(&g_nflag, 1);
            g_list[slot] = t0;
        }
        g_idx[t0 + 8] = i1_1;
        if (b1_1 - b2_1 < MARGIN) {
            int slot = atomicAdd(&g_nflag, 1);
            g_list[slot] = t0 + 8;
        }
    }
}

// ---------------------------------------------------------------------------
// exact fp32 re-argmax for flagged tokens: one 256-thread block per token,
// pulled from the compacted list. Empty list -> immediate exit.
__global__ __launch_bounds__(256)
void k_refine(const float* __restrict__ z, const float* __restrict__ emb) {
    __shared__ float sx[C_DIM];
    __shared__ float rb[8];
    __shared__ int   ri[8];
    const int tid = threadIdx.x;
    const int lane = tid & 31;
    const int wid = tid >> 5;
    const int nf = g_nflag;

    for (int it = blockIdx.x; it < nf; it += gridDim.x) {
        const int t = g_list[it];
        const float* zp = z + (size_t)(t >> 10) * (C_DIM * HW) + (t & 1023);
        if (tid < C_DIM) sx[tid] = zp[tid * HW];
        __syncthreads();

        float best = -3.4e38f;
        int bidx = K_CODES;
        for (int k = tid; k < K_CODES; k += 256) {
            const float4* e4 = (const float4*)(emb + (size_t)k * C_DIM);
            float s = 0.0f;
            #pragma unroll
            for (int j = 0; j < 16; j++) {
                float4 e = e4[j];
                s += sx[4 * j] * e.x + sx[4 * j + 1] * e.y
                   + sx[4 * j + 2] * e.z + sx[4 * j + 3] * e.w;
            }
            s -= g_hn[k];
            if (s > best) { best = s; bidx = k; }   // ascending k: > keeps first
        }
        #pragma unroll
        for (int o = 16; o > 0; o >>= 1) {
            float ob = __shfl_xor_sync(0xffffffffu, best, o);
            int   oi = __shfl_xor_sync(0xffffffffu, bidx, o);
            if (ob > best || (ob == best && oi < bidx)) { best = ob; bidx = oi; }
        }
        if (lane == 0) { rb[wid] = best; ri[wid] = bidx; }
        __syncthreads();
        if (tid == 0) {
            float bb = rb[0]; int bi2 = ri[0];
            #pragma unroll
            for (int w2 = 1; w2 < 8; w2++) {
                if (rb[w2] > bb || (rb[w2] == bb && ri[w2] < bi2)) {
                    bb = rb[w2]; bi2 = ri[w2];
                }
            }
            g_idx[t] = bi2;
        }
        __syncthreads();   // protect sx/rb before next iteration
    }
}

// ---------------------------------------------------------------------------
// epilogue: indices, z_q, z_q_st, counts, dw  (4 threads per token)
__global__ __launch_bounds__(256)
void k_epi(const float* __restrict__ z, const float* __restrict__ emb,
           float* __restrict__ out) {
    const int gid = blockIdx.x * blockDim.x + threadIdx.x;
    const int t = gid >> 2;
    const int part = gid & 3;
    if (t >= N_TOK) return;
    const int b = t >> 10;
    const int hw = t & 1023;
    const float* zp = z + (size_t)b * (C_DIM * HW) + hw;

    int bi = g_idx[t];
    if (part == 0) {
        out[O_IDX + t] = (float)bi;
        atomicAdd(&g_counts[bi], 1.0f);
    }

    const float4* er = (const float4*)(emb + (size_t)bi * C_DIM) + part * 4;
    float* dwp = g_dw + (size_t)bi * C_DIM;
    float* zq   = out + O_ZQ   + (size_t)b * (C_DIM * HW) + hw;
    float* zqst = out + O_ZQST + (size_t)b * (C_DIM * HW) + hw;

    #pragma unroll
    for (int j = 0; j < 4; j++) {
        float4 q = er[j];
        int c = part * 16 + 4 * j;
        float x0 = zp[(c + 0) * HW];
        float x1 = zp[(c + 1) * HW];
        float x2 = zp[(c + 2) * HW];
        float x3 = zp[(c + 3) * HW];
        zq[(c + 0) * HW] = q.x;
        zq[(c + 1) * HW] = q.y;
        zq[(c + 2) * HW] = q.z;
        zq[(c + 3) * HW] = q.w;
        zqst[(c + 0) * HW] = x0 + (q.x - x0);
        zqst[(c + 1) * HW] = x1 + (q.y - x1);
        zqst[(c + 2) * HW] = x2 + (q.z - x2);
        zqst[(c + 3) * HW] = x3 + (q.w - x3);
        atomicAdd(dwp + c + 0, x0);
        atomicAdd(dwp + c + 1, x1);
        atomicAdd(dwp + c + 2, x2);
        atomicAdd(dwp + c + 3, x3);
    }
}

// ---------------------------------------------------------------------------
__global__ void k_cs(const float* __restrict__ cs, float* __restrict__ out) {
    const float OMD = 0.01f;
    int tid = threadIdx.x;
    float loc = 0.0f;
    for (int k = tid; k < K_CODES; k += 1024) {
        float v = 0.99f * cs[k] + OMD * g_counts[k];
        out[O_CS + k] = v;
        loc += v;
    }
    __shared__ float red[32];
    #pragma unroll
    for (int o = 16; o > 0; o >>= 1) loc += __shfl_xor_sync(0xffffffffu, loc, o);
    if ((tid & 31) == 0) red[tid >> 5] = loc;
    __syncthreads();
    if (tid < 32) {
        float v = red[tid];
        #pragma unroll
        for (int o = 16; o > 0; o >>= 1) v += __shfl_xor_sync(0xffffffffu, v, o);
        if (tid == 0) g_n = v;
    }
}

__global__ void k_emb(const float* __restrict__ cs, const float* __restrict__ avg,
                      float* __restrict__ out) {
    const float OMD = 0.01f;
    const float EPSF = 1e-5f;
    int i = blockIdx.x * blockDim.x + threadIdx.x;
    if (i >= K_CODES * C_DIM) return;
    int k = i >> 6;
    float ncs = 0.99f * cs[k] + OMD * g_counts[k];
    float navg = 0.99f * avg[i] + OMD * g_dw[i];
    float n = g_n;
    float denom = (ncs + EPSF) / (n + (float)K_CODES * EPSF) * n;
    out[O_EMB + i] = navg / denom;
    out[O_AVG + i] = navg;
}

// ---------------------------------------------------------------------------
extern "C" void kernel_launch(void* const* d_in, const int* in_sizes, int n_in,
                              void* d_out, int out_size) {
    const float* z   = (const float*)d_in[0];
    const float* emb = (const float*)d_in[1];
    const float* cs  = (const float*)d_in[2];
    const float* avg = (const float*)d_in[3];
    float* out = (float*)d_out;

    cudaFuncSetAttribute(k_dist, cudaFuncAttributeMaxDynamicSharedMemorySize, SMEM_TOTAL);

    k_init<<<(K_CODES * C_DIM + 255) / 256, 256>>>();
    k_splitE<<<(K_CODES * 32 + 255) / 256, 256>>>(emb);
    k_dist<<<N_TOK / MTILE, TPB, SMEM_TOTAL>>>(z);
    k_refine<<<64, 256>>>(z, emb);
    k_epi<<<(4 * N_TOK + 255) / 256, 256>>>(z, emb, out);
    k_cs<<<1, 1024>>>(cs, out);
    k_emb<<<(K_CODES * C_DIM + 255) / 256, 256>>>(cs, avg, out);
}

// round 8
// speedup vs baseline: 3.7539x; 1.3471x over previous
#include <cuda_runtime.h>
#include <cuda_fp16.h>
#include <cstdint>

#define K_CODES 8192
#define C_DIM   64
#define N_TOK   16384
#define HW      1024
#define TPB     256
#define MTILE   128                  // tokens per CTA
#define NTILE   64                   // codes per tile
#define NTILES  (K_CODES / NTILE)    // 128
#define MARGIN  1e-4f

// output layout (float32, concatenated in reference return order)
#define O_ZQST 0
#define O_IDX  1048576
#define O_ZQ   1064960
#define O_EMB  2113536
#define O_CS   2637824
#define O_AVG  2646016

// smem layout for k_dist
#define SM_A    0                        // 2 comps x 128 rows x 128B = 32768
#define SM_B    32768                    // 2 bufs x 2 comps x 64 rows x 128B = 32768
#define SM_HN   65536                    // 2 x 256B
#define SMEM_TOTAL (65536 + 512 + 128)

typedef unsigned long long u64;
typedef unsigned int u32;

static __device__ __half g_Eh[K_CODES * C_DIM];
static __device__ __half g_Er[K_CODES * C_DIM];
static __device__ float g_hn[K_CODES];
static __device__ int   g_idx[N_TOK];
static __device__ int   g_flag[N_TOK];
static __device__ u64   g_key[N_TOK];
static __device__ int   g_list[N_TOK];
static __device__ int   g_nflag;
static __device__ float g_counts[K_CODES];
static __device__ float g_dw[K_CODES * C_DIM];
static __device__ float g_n;

// ---------------------------------------------------------------- helpers
__device__ __forceinline__ uint32_t smem_u32(const void* p) {
    uint32_t a;
    asm("{ .reg .u64 t; cvta.to.shared.u64 t, %1; cvt.u32.u64 %0, t; }"
        : "=r"(a) : "l"(p));
    return a;
}
__device__ __forceinline__ void cp_async16(uint32_t saddr, const void* gmem) {
    asm volatile("cp.async.cg.shared.global [%0], [%1], 16;\n" :: "r"(saddr), "l"(gmem));
}
#define CP_COMMIT() asm volatile("cp.async.commit_group;\n" ::: "memory")
#define CP_WAIT(n)  asm volatile("cp.async.wait_group %0;\n" :: "n"(n) : "memory")

__device__ __forceinline__ uint32_t sw128(uint32_t off) {
    return off ^ ((off >> 3) & 0x70);
}
__device__ __forceinline__ void ldsm4(u32& r0, u32& r1, u32& r2, u32& r3, uint32_t addr) {
    asm volatile("ldmatrix.sync.aligned.m8n8.x4.shared.b16 {%0,%1,%2,%3}, [%4];"
                 : "=r"(r0), "=r"(r1), "=r"(r2), "=r"(r3) : "r"(addr));
}
__device__ __forceinline__ void mma16816(float& d0, float& d1, float& d2, float& d3,
                                         u32 a0, u32 a1, u32 a2, u32 a3,
                                         u32 b0, u32 b1) {
    asm volatile("mma.sync.aligned.m16n8k16.row.col.f32.f16.f16.f32 "
                 "{%0,%1,%2,%3}, {%4,%5,%6,%7}, {%8,%9}, {%0,%1,%2,%3};"
                 : "+f"(d0), "+f"(d1), "+f"(d2), "+f"(d3)
                 : "r"(a0), "r"(a1), "r"(a2), "r"(a3), "r"(b0), "r"(b1));
}
// monotone map: float score -> u32 preserving order
__device__ __forceinline__ u32 fmono(float s) {
    u32 u = __float_as_uint(s);
    return (s < 0.0f) ? ~u : (u | 0x80000000u);
}

// ---------------------------------------------------------------------------
__global__ void k_init() {
    int i = blockIdx.x * blockDim.x + threadIdx.x;
    if (i < K_CODES) g_counts[i] = 0.0f;
    if (i < K_CODES * C_DIM) g_dw[i] = 0.0f;
    if (i < N_TOK) g_flag[i] = 0;
    if (i == 0) { g_nflag = 0; g_n = 0.0f; }
}

// split embedding into 2 fp16 components + half squared norms
__global__ void k_splitE(const float* __restrict__ emb) {
    int w = (blockIdx.x * blockDim.x + threadIdx.x) >> 5;
    int lane = threadIdx.x & 31;
    if (w >= K_CODES) return;
    float s = 0.0f;
    #pragma unroll
    for (int half = 0; half < 2; half++) {
        int c = lane + half * 32;
        float x = emb[w * C_DIM + c];
        s += x * x;
        __half h = __float2half_rn(x);
        float r = x - __half2float(h);
        g_Eh[w * C_DIM + c] = h;
        g_Er[w * C_DIM + c] = __float2half_rn(r);
    }
    #pragma unroll
    for (int o = 16; o > 0; o >>= 1) s += __shfl_xor_sync(0xffffffffu, s, o);
    if (lane == 0) g_hn[w] = 0.5f * s;
}

// ---------------------------------------------------------------------------
// S[t][k] = x_t . e_k via 3-term fp16 split, warp mma.sync; fused argmax+top2.
__global__ void __launch_bounds__(TPB, 1) k_dist(const float* __restrict__ z) {
    extern __shared__ char smem[];
    const uint32_t sb = smem_u32(smem);
    const int tid = threadIdx.x;
    const int lane = tid & 31;
    const int w = tid >> 5;

    // --- load 128 tokens, 2-way fp16 split into sA (SW128 rows) ---
    {
        int r = tid & 127;            // token row in tile
        int half = tid >> 7;          // dims 0-31 / 32-63
        int t = blockIdx.x * MTILE + r;
        const float* zp = z + (size_t)(t >> 10) * (C_DIM * HW) + (t & 1023);
        #pragma unroll
        for (int j = 0; j < 32; j++) {
            int c = half * 32 + j;
            float x = zp[c * HW];
            __half h = __float2half_rn(x);
            float rr = x - __half2float(h);
            uint32_t off = sw128((uint32_t)(r * 128 + c * 2));
            *(__half*)(smem + SM_A + off) = h;
            *(__half*)(smem + SM_A + 16384 + off) = __float2half_rn(rr);
        }
    }
    __syncthreads();

    // --- preload A fragments: 2 comps x 4 ksteps x (m16k16 = 4 regs) ---
    u32 afr[2][4][4];
    {
        int arow = w * 16 + (lane & 7) + ((lane >> 3) & 1) * 8;
        int akb  = (lane >> 4) * 16;
        #pragma unroll
        for (int c = 0; c < 2; c++)
            #pragma unroll
            for (int q = 0; q < 4; q++) {
                uint32_t addr = sb + SM_A + c * 16384 +
                                sw128((uint32_t)(arow * 128 + q * 32 + akb));
                ldsm4(afr[c][q][0], afr[c][q][1], afr[c][q][2], afr[c][q][3], addr);
            }
    }

    // --- tile loader (2 comps + hn) ---
    auto load_tile = [&](int tile, int bufi) {
        const char* srcs[2] = {(const char*)g_Eh, (const char*)g_Er};
        #pragma unroll
        for (int c = 0; c < 2; c++) {
            const char* src = srcs[c] + (size_t)tile * (NTILE * C_DIM * 2);
            uint32_t dst = sb + SM_B + (uint32_t)(bufi * 2 + c) * 8192u;
            #pragma unroll
            for (int u = 0; u < 2; u++) {
                uint32_t off = (uint32_t)(u * TPB + tid) * 16u;
                cp_async16(dst + sw128(off), src + off);
            }
        }
        if (tid < 16)
            cp_async16(sb + SM_HN + bufi * 256 + tid * 16,
                       (const char*)(g_hn + tile * NTILE) + tid * 16);
    };

    // per-lane B ldmatrix address components
    const int brow = (lane & 7) + ((lane >> 4) & 1) * 8;
    const int bkb  = ((lane >> 3) & 1) * 16;

    // per-lane top-2 for each of the two token rows this lane touches
    float b1_0 = -3.4e38f, b2_0 = -3.4e38f;
    float b1_1 = -3.4e38f, b2_1 = -3.4e38f;
    int i1_0 = 0, i1_1 = 0;

    load_tile(0, 0); CP_COMMIT();
    load_tile(1, 1); CP_COMMIT();

    for (int ci = 0; ci < NTILES; ci++) {
        const int buf = ci & 1;
        if (ci + 1 < NTILES) { CP_WAIT(1); } else { CP_WAIT(0); }
        __syncthreads();

        float acc[8][4];
        #pragma unroll
        for (int g = 0; g < 8; g++)
            #pragma unroll
            for (int v = 0; v < 4; v++) acc[g][v] = 0.0f;

        #pragma unroll
        for (int q = 0; q < 4; q++) {
            u32 bfr[8][2];
            // B comp 0 (h_e): terms hh (A0) and rh (A1)
            uint32_t b0base = sb + SM_B + (uint32_t)(buf * 2) * 8192u;
            #pragma unroll
            for (int g2 = 0; g2 < 4; g2++) {
                uint32_t addr = b0base +
                    sw128((uint32_t)((g2 * 16 + brow) * 128 + q * 32 + bkb));
                ldsm4(bfr[2 * g2][0], bfr[2 * g2][1],
                      bfr[2 * g2 + 1][0], bfr[2 * g2 + 1][1], addr);
            }
            #pragma unroll
            for (int g = 0; g < 8; g++) {
                mma16816(acc[g][0], acc[g][1], acc[g][2], acc[g][3],
                         afr[0][q][0], afr[0][q][1], afr[0][q][2], afr[0][q][3],
                         bfr[g][0], bfr[g][1]);
                mma16816(acc[g][0], acc[g][1], acc[g][2], acc[g][3],
                         afr[1][q][0], afr[1][q][1], afr[1][q][2], afr[1][q][3],
                         bfr[g][0], bfr[g][1]);
            }
            // B comp 1 (r_e): term hr (A0)
            uint32_t b1base = sb + SM_B + (uint32_t)(buf * 2 + 1) * 8192u;
            #pragma unroll
            for (int g2 = 0; g2 < 4; g2++) {
                uint32_t addr = b1base +
                    sw128((uint32_t)((g2 * 16 + brow) * 128 + q * 32 + bkb));
                ldsm4(bfr[2 * g2][0], bfr[2 * g2][1],
                      bfr[2 * g2 + 1][0], bfr[2 * g2 + 1][1], addr);
            }
            #pragma unroll
            for (int g = 0; g < 8; g++)
                mma16816(acc[g][0], acc[g][1], acc[g][2], acc[g][3],
                         afr[0][q][0], afr[0][q][1], afr[0][q][2], afr[0][q][3],
                         bfr[g][0], bfr[g][1]);
        }

        // fused top-2 epilogue: score = x.e - 0.5||e||^2
        const float* hnp = (const float*)(smem + SM_HN + buf * 256);
        const int colbase = ci * NTILE + 2 * (lane & 3);
        #pragma unroll
        for (int g = 0; g < 8; g++) {
            int lc = g * 8 + 2 * (lane & 3);
            float h0 = hnp[lc], h1 = hnp[lc + 1];
            int c0 = colbase + g * 8, c1 = c0 + 1;
            float s0 = acc[g][0] - h0;
            float s1 = acc[g][1] - h1;
            float s2 = acc[g][2] - h0;
            float s3 = acc[g][3] - h1;
            if (s0 > b1_0) { b2_0 = b1_0; b1_0 = s0; i1_0 = c0; }
            else if (s0 > b2_0) b2_0 = s0;
            if (s1 > b1_0) { b2_0 = b1_0; b1_0 = s1; i1_0 = c1; }
            else if (s1 > b2_0) b2_0 = s1;
            if (s2 > b1_1) { b2_1 = b1_1; b1_1 = s2; i1_1 = c0; }
            else if (s2 > b2_1) b2_1 = s2;
            if (s3 > b1_1) { b2_1 = b1_1; b1_1 = s3; i1_1 = c1; }
            else if (s3 > b2_1) b2_1 = s3;
        }

        __syncthreads();   // all warps done reading buf
        if (ci + 2 < NTILES) { load_tile(ci + 2, buf); CP_COMMIT(); }
    }

    // merge top-2 across the 4 lanes sharing each row
    #pragma unroll
    for (int o = 1; o <= 2; o <<= 1) {
        float ob1 = __shfl_xor_sync(0xffffffffu, b1_0, o);
        float ob2 = __shfl_xor_sync(0xffffffffu, b2_0, o);
        int   oi1 = __shfl_xor_sync(0xffffffffu, i1_0, o);
        if (ob1 > b1_0 || (ob1 == b1_0 && oi1 < i1_0)) {
            b2_0 = fmaxf(b1_0, ob2); b1_0 = ob1; i1_0 = oi1;
        } else {
            b2_0 = fmaxf(b2_0, ob1);
        }
        ob1 = __shfl_xor_sync(0xffffffffu, b1_1, o);
        ob2 = __shfl_xor_sync(0xffffffffu, b2_1, o);
        oi1 = __shfl_xor_sync(0xffffffffu, i1_1, o);
        if (ob1 > b1_1 || (ob1 == b1_1 && oi1 < i1_1)) {
            b2_1 = fmaxf(b1_1, ob2); b1_1 = ob1; i1_1 = oi1;
        } else {
            b2_1 = fmaxf(b2_1, ob1);
        }
    }
    if ((lane & 3) == 0) {
        int r = w * 16 + (lane >> 2);
        int t0 = blockIdx.x * MTILE + r;
        g_idx[t0] = i1_0;
        if (b1_0 - b2_0 < MARGIN) {
            g_flag[t0] = 1;
            g_key[t0] = 0xFFFFFFFFFFFFFFFFULL;
            int slot = atomicAdd(&g_nflag, 1);
            g_list[slot] = t0;
        }
        g_idx[t0 + 8] = i1_1;
        if (b1_1 - b2_1 < MARGIN) {
            g_flag[t0 + 8] = 1;
            g_key[t0 + 8] = 0xFFFFFFFFFFFFFFFFULL;
            int slot = atomicAdd(&g_nflag, 1);
            g_list[slot] = t0 + 8;
        }
    }
}

// ---------------------------------------------------------------------------
// exact fp32 re-argmax for flagged tokens, parallelized across the chip:
// work item = (token, 128-code slice); merge via atomicMin on sortable key.
__global__ __launch_bounds__(256)
void k_refine(const float* __restrict__ z, const float* __restrict__ emb) {
    __shared__ float sx[C_DIM];
    __shared__ u64 rk[8];
    const int tid = threadIdx.x;
    const int lane = tid & 31;
    const int wid = tid >> 5;
    const int nf = g_nflag;
    if (nf == 0) return;

    for (int wk = blockIdx.x; wk < nf * 64; wk += gridDim.x) {
        const int it = wk >> 6;
        const int slice = wk & 63;
        const int t = g_list[it];
        __syncthreads();   // protect sx from previous iteration
        if (tid < C_DIM) {
            const float* zp = z + (size_t)(t >> 10) * (C_DIM * HW) + (t & 1023);
            sx[tid] = zp[tid * HW];
        }
        __syncthreads();

        u64 key = 0xFFFFFFFFFFFFFFFFULL;
        if (tid < 128) {
            int k = slice * 128 + tid;
            const float4* e4 = (const float4*)(emb + (size_t)k * C_DIM);
            float s = 0.0f;
            #pragma unroll
            for (int j = 0; j < 16; j++) {
                float4 e = e4[j];
                s += sx[4 * j] * e.x + sx[4 * j + 1] * e.y
                   + sx[4 * j + 2] * e.z + sx[4 * j + 3] * e.w;
            }
            s -= g_hn[k];
            key = ((u64)(~fmono(s)) << 32) | (u32)k;
        }
        #pragma unroll
        for (int o = 16; o > 0; o >>= 1) {
            u64 ok = __shfl_xor_sync(0xffffffffu, key, o);
            if (ok < key) key = ok;
        }
        if (lane == 0) rk[wid] = key;
        __syncthreads();
        if (tid == 0) {
            u64 kmin = rk[0];
            #pragma unroll
            for (int w2 = 1; w2 < 8; w2++) if (rk[w2] < kmin) kmin = rk[w2];
            atomicMin(&g_key[t], kmin);
        }
    }
}

// ---------------------------------------------------------------------------
// epilogue: indices, z_q, z_q_st, counts, dw  (4 threads per token)
__global__ __launch_bounds__(256)
void k_epi(const float* __restrict__ z, const float* __restrict__ emb,
           float* __restrict__ out) {
    const int gid = blockIdx.x * blockDim.x + threadIdx.x;
    const int t = gid >> 2;
    const int part = gid & 3;
    if (t >= N_TOK) return;
    const int b = t >> 10;
    const int hw = t & 1023;
    const float* zp = z + (size_t)b * (C_DIM * HW) + hw;

    int bi = g_flag[t] ? (int)(u32)(g_key[t] & 0xFFFFFFFFULL) : g_idx[t];
    if (part == 0) {
        out[O_IDX + t] = (float)bi;
        atomicAdd(&g_counts[bi], 1.0f);
    }

    const float4* er = (const float4*)(emb + (size_t)bi * C_DIM) + part * 4;
    float* dwp = g_dw + (size_t)bi * C_DIM;
    float* zq   = out + O_ZQ   + (size_t)b * (C_DIM * HW) + hw;
    float* zqst = out + O_ZQST + (size_t)b * (C_DIM * HW) + hw;

    #pragma unroll
    for (int j = 0; j < 4; j++) {
        float4 q = er[j];
        int c = part * 16 + 4 * j;
        float x0 = zp[(c + 0) * HW];
        float x1 = zp[(c + 1) * HW];
        float x2 = zp[(c + 2) * HW];
        float x3 = zp[(c + 3) * HW];
        zq[(c + 0) * HW] = q.x;
        zq[(c + 1) * HW] = q.y;
        zq[(c + 2) * HW] = q.z;
        zq[(c + 3) * HW] = q.w;
        zqst[(c + 0) * HW] = x0 + (q.x - x0);
        zqst[(c + 1) * HW] = x1 + (q.y - x1);
        zqst[(c + 2) * HW] = x2 + (q.z - x2);
        zqst[(c + 3) * HW] = x3 + (q.w - x3);
        atomicAdd(dwp + c + 0, x0);
        atomicAdd(dwp + c + 1, x1);
        atomicAdd(dwp + c + 2, x2);
        atomicAdd(dwp + c + 3, x3);
    }
}

// ---------------------------------------------------------------------------
// new_cluster_size + partial sums of n (32 blocks, atomicAdd merge)
__global__ __launch_bounds__(256)
void k_cs(const float* __restrict__ cs, float* __restrict__ out) {
    const float OMD = 0.01f;
    int i = blockIdx.x * 256 + threadIdx.x;   // 8192 total
    float v = 0.99f * cs[i] + OMD * g_counts[i];
    out[O_CS + i] = v;
    #pragma unroll
    for (int o = 16; o > 0; o >>= 1) v += __shfl_xor_sync(0xffffffffu, v, o);
    __shared__ float red[8];
    if ((threadIdx.x & 31) == 0) red[threadIdx.x >> 5] = v;
    __syncthreads();
    if (threadIdx.x == 0) {
        float s = red[0];
        #pragma unroll
        for (int w2 = 1; w2 < 8; w2++) s += red[w2];
        atomicAdd(&g_n, s);
    }
}

__global__ void k_emb(const float* __restrict__ cs, const float* __restrict__ avg,
                      float* __restrict__ out) {
    const float OMD = 0.01f;
    const float EPSF = 1e-5f;
    int i = blockIdx.x * blockDim.x + threadIdx.x;
    if (i >= K_CODES * C_DIM) return;
    int k = i >> 6;
    float ncs = 0.99f * cs[k] + OMD * g_counts[k];
    float navg = 0.99f * avg[i] + OMD * g_dw[i];
    float n = g_n;
    float denom = (ncs + EPSF) / (n + (float)K_CODES * EPSF) * n;
    out[O_EMB + i] = navg / denom;
    out[O_AVG + i] = navg;
}

// ---------------------------------------------------------------------------
extern "C" void kernel_launch(void* const* d_in, const int* in_sizes, int n_in,
                              void* d_out, int out_size) {
    const float* z   = (const float*)d_in[0];
    const float* emb = (const float*)d_in[1];
    const float* cs  = (const float*)d_in[2];
    const float* avg = (const float*)d_in[3];
    float* out = (float*)d_out;

    cudaFuncSetAttribute(k_dist, cudaFuncAttributeMaxDynamicSharedMemorySize, SMEM_TOTAL);

    k_init<<<(K_CODES * C_DIM + 255) / 256, 256>>>();
    k_splitE<<<(K_CODES * 32 + 255) / 256, 256>>>(emb);
    k_dist<<<N_TOK / MTILE, TPB, SMEM_TOTAL>>>(z);
    k_refine<<<128, 256>>>(z, emb);
    k_epi<<<(4 * N_TOK + 255) / 256, 256>>>(z, emb, out);
    k_cs<<<K_CODES / 256, 256>>>(cs, out);
    k_emb<<<(K_CODES * C_DIM + 255) / 256, 256>>>(cs, avg, out);
}